// round 3
// baseline (speedup 1.0000x reference)
#include <cuda_runtime.h>
#include <cstdint>
#include <cstddef>

// Problem sizes (fixed)
//  B=128, S=2048, I=256, H=512, O=256
// Persistent-LSTM design:
//  128 CTAs = 4 batch-bands(32 rows) x 32 column-CTAs(16 h-cols, all 4 gates)
//  Per-CTA SMEM weight tile: [K=768][64 gate-cols] tf32, resident all 2048 steps
//  Per-step: A=[h_{t-1} | x_t] (K order: x first 256, then h 512) staged in
//  64-wide K chunks via cp.async.cg (L2-only => cross-CTA h coherence),
//  tf32 m16n8k8 mma, fp32 cell update, h double-buffered by step parity,
//  per-band 32-CTA software barrier.

#define TB 256

static __device__ float g_h[2][128 * 512];
static __device__ int g_cnt[128];
static __device__ volatile int g_flag[128];

__device__ __forceinline__ void cp16(void* dst, const void* src) {
    unsigned d = (unsigned)__cvta_generic_to_shared(dst);
    asm volatile("cp.async.cg.shared.global [%0], [%1], 16;\n" ::"r"(d), "l"(src));
}
__device__ __forceinline__ void cp_commit() { asm volatile("cp.async.commit_group;\n"); }
__device__ __forceinline__ void cp_wait0() { asm volatile("cp.async.wait_group 0;\n"); }

__device__ __forceinline__ unsigned f2tf(float x) {
    unsigned r;
    asm("cvt.rna.tf32.f32 %0, %1;" : "=r"(r) : "f"(x));
    return r;
}
__device__ __forceinline__ void mma_tf32(float c[4], unsigned a0, unsigned a1, unsigned a2,
                                         unsigned a3, unsigned b0, unsigned b1) {
    asm volatile(
        "mma.sync.aligned.m16n8k8.row.col.f32.tf32.tf32.f32 "
        "{%0,%1,%2,%3},{%4,%5,%6,%7},{%8,%9},{%0,%1,%2,%3};"
        : "+f"(c[0]), "+f"(c[1]), "+f"(c[2]), "+f"(c[3])
        : "r"(a0), "r"(a1), "r"(a2), "r"(a3), "r"(b0), "r"(b1));
}
__device__ __forceinline__ void stcg(float* p, float v) {
    asm volatile("st.global.cg.f32 [%0], %1;" ::"l"(p), "f"(v));
}

// SMEM layout (floats):
//  Ws  : 64 * 772          (weight tile, padded stride 772 for bank-conflict-free B frags)
//  As0 : 32 * 68           (A chunk buffer 0, padded stride 68)
//  As1 : 32 * 68
//  Cs  : 32 * 68           (gate preactivations)
//  cst : 512               (cell state, 32 rows x 16 h-cols)
//  bs  : 64                (biases, gate*16+hc order)
#define SMEM_FLOATS (64 * 772 + 3 * 32 * 68 + 512 + 64)

__global__ void __launch_bounds__(TB, 1)
lstm_persist(const float* __restrict__ x,
             const float* __restrict__ W_ix, const float* __restrict__ W_fx,
             const float* __restrict__ W_ox, const float* __restrict__ W_gx,
             const float* __restrict__ W_ih, const float* __restrict__ b_ih,
             const float* __restrict__ W_fh, const float* __restrict__ b_fh,
             const float* __restrict__ W_oh, const float* __restrict__ b_oh,
             const float* __restrict__ W_gh, const float* __restrict__ b_gh) {
    extern __shared__ float sm[];
    float* Ws = sm;
    float* As0 = Ws + 64 * 772;
    float* As1 = As0 + 32 * 68;
    float* Cs = As1 + 32 * 68;
    float* cst = Cs + 32 * 68;
    float* bs = cst + 512;

    const int tid = threadIdx.x;
    const int cta = blockIdx.x;
    const int band = cta >> 5;   // 0..3
    const int col = cta & 31;    // 0..31
    const int hc0 = col * 16;    // first h-column owned
    const int brow0 = band * 32; // first batch row of band

    const float* Whp[4] = {W_ih, W_fh, W_oh, W_gh};
    const float* Wxp[4] = {W_ix, W_fx, W_ox, W_gx};
    const float* bbp[4] = {b_ih, b_fh, b_oh, b_gh};

    // ---- Prologue: load + tf32-round weight tile. n = gate*16+hc.
    // K order: k in [0,256) -> x weights, k in [256,768) -> h weights.
    for (int idx = tid; idx < 64 * 768; idx += TB) {
        int n = idx / 768;
        int k = idx - n * 768;
        int gate = n >> 4;
        int hc = hc0 + (n & 15);
        float v = (k < 256) ? Wxp[gate][hc * 256 + k] : Whp[gate][hc * 512 + (k - 256)];
        ((unsigned*)Ws)[n * 772 + k] = f2tf(v);
    }
    for (int i = tid; i < 64; i += TB) bs[i] = bbp[i >> 4][hc0 + (i & 15)];
    for (int i = tid; i < 512; i += TB) cst[i] = 0.f;
    __syncthreads();

    const int lane = tid & 31;
    const int w = tid >> 5;
    const int g = lane >> 2; // group id 0..7
    const int tq = lane & 3; // thread-in-group
    const int wr0 = (w & 1) * 16;  // warp row base (0 or 16)
    const int wc0 = (w >> 1) * 16; // warp col base (0,16,32,48)

    // ---- Prologue stage: chunk 0 (x cols 0..63) of step t=1 into As0
    for (int it = tid; it < 512; it += TB) {
        int r = it >> 4, q = it & 15;
        cp16(As0 + r * 68 + q * 4,
             x + ((size_t)(brow0 + r) * 2048 + 0) * 256 + q * 4);
    }
    cp_commit();

    int curbuf = 0; // buffer holding the chunk about to be consumed
    for (int t = 1; t <= 2048; ++t) {
        const float* hprev = g_h[(t - 1) & 1];
        float* hcur = g_h[t & 1];

        float acc[2][4];
#pragma unroll
        for (int n = 0; n < 2; n++)
#pragma unroll
            for (int j = 0; j < 4; j++) acc[n][j] = 0.f;

        for (int kc = 0; kc < 12; ++kc) {
            cp_wait0();
            __syncthreads(); // chunk kc visible to all; everyone done with bufn

            float* bufn = curbuf ? As0 : As1;
            // Issue next chunk (overlaps the mma below).
            if (kc < 11) {
                int nc = kc + 1;
                if (nc < 4) { // x chunk
                    for (int it = tid; it < 512; it += TB) {
                        int r = it >> 4, q = it & 15;
                        cp16(bufn + r * 68 + q * 4,
                             x + ((size_t)(brow0 + r) * 2048 + (t - 1)) * 256 + nc * 64 + q * 4);
                    }
                } else { // h chunk (L2-coherent via .cg)
                    for (int it = tid; it < 512; it += TB) {
                        int r = it >> 4, q = it & 15;
                        cp16(bufn + r * 68 + q * 4,
                             hprev + (brow0 + r) * 512 + (nc - 4) * 64 + q * 4);
                    }
                }
                cp_commit();
            } else if (t < 2048) {
                // Prefetch next step's chunk 0 = x(t) : no dependency on h(t).
                for (int it = tid; it < 512; it += TB) {
                    int r = it >> 4, q = it & 15;
                    cp16(bufn + r * 68 + q * 4,
                         x + ((size_t)(brow0 + r) * 2048 + t) * 256 + q * 4);
                }
                cp_commit();
            } else {
                cp_commit(); // empty group keeps wait_group balanced
            }

            // mma over chunk kc
            const unsigned* Au = (const unsigned*)(curbuf ? As1 : As0);
            const unsigned* Wu = (const unsigned*)Ws;
#pragma unroll
            for (int kk = 0; kk < 8; ++kk) {
                int kb = kk * 8 + tq;
                unsigned a0 = Au[(wr0 + g) * 68 + kb];
                unsigned a1 = Au[(wr0 + g + 8) * 68 + kb];
                unsigned a2 = Au[(wr0 + g) * 68 + kb + 4];
                unsigned a3 = Au[(wr0 + g + 8) * 68 + kb + 4];
#pragma unroll
                for (int nt = 0; nt < 2; ++nt) {
                    int wn = (wc0 + nt * 8 + g) * 772 + kc * 64 + kk * 8 + tq;
                    unsigned b0 = Wu[wn];
                    unsigned b1 = Wu[wn + 4];
                    mma_tf32(acc[nt], a0, a1, a2, a3, b0, b1);
                }
            }
            curbuf ^= 1;
        }

        // ---- Write gate preactivations to Cs (each warp its own cells)
#pragma unroll
        for (int nt = 0; nt < 2; ++nt) {
            int c0 = wc0 + nt * 8 + 2 * tq;
            Cs[(wr0 + g) * 68 + c0] = acc[nt][0];
            Cs[(wr0 + g) * 68 + c0 + 1] = acc[nt][1];
            Cs[(wr0 + g + 8) * 68 + c0] = acc[nt][2];
            Cs[(wr0 + g + 8) * 68 + c0 + 1] = acc[nt][3];
        }
        __syncthreads();

        // ---- Cell update (fp32), h store (st.cg -> L2)
        for (int it = tid; it < 512; it += TB) {
            int r = it >> 4, hc = it & 15;
            const float* Crow = Cs + r * 68;
            float zi = Crow[hc] + bs[hc];
            float zf = Crow[16 + hc] + bs[16 + hc];
            float zo = Crow[32 + hc] + bs[32 + hc];
            float zg = Crow[48 + hc] + bs[48 + hc];
            float gi = 1.f / (1.f + __expf(-zi));
            float gf = 1.f / (1.f + __expf(-zf));
            float go = 1.f / (1.f + __expf(-zo));
            float gg = tanhf(zg);
            float c = gg * gi + cst[it] * gf;
            cst[it] = c;
            float h = tanhf(c) * go;
            stcg(&hcur[(brow0 + r) * 512 + hc0 + hc], h);
        }
        __threadfence(); // every thread: own h stores visible at GPU scope
        __syncthreads();

        // ---- Per-band barrier (32 CTAs)
        if (tid == 0) {
            int prev = atomicAdd(&g_cnt[band * 32], 1);
            if (prev == 31) {
                atomicExch(&g_cnt[band * 32], 0);
                __threadfence();
                g_flag[band * 32] = t;
            } else {
                while (g_flag[band * 32] < t) { __nanosleep(64); }
                __threadfence();
            }
        }
        __syncthreads();
    }
}

__global__ void init_k() {
    int i = blockIdx.x * blockDim.x + threadIdx.x;
    if (i < 128) {
        g_cnt[i] = 0;
        g_flag[i] = 0;
    }
    for (int j = i; j < 128 * 512; j += gridDim.x * blockDim.x) g_h[0][j] = 0.f;
}

// out[b][o] = sum_k h_final[b][k] * W_ph[o][k] + b_ph[o]   (h_final = g_h[0], t=2048 even)
__global__ void __launch_bounds__(256) proj_k(const float* __restrict__ W_ph,
                                              const float* __restrict__ b_ph,
                                              float* __restrict__ out) {
    __shared__ float hs[512];
    int b = blockIdx.x;
    const float* hrow = g_h[0] + b * 512;
    for (int i = threadIdx.x; i < 512; i += 256) hs[i] = hrow[i];
    __syncthreads();
    int o = threadIdx.x;
    const float* wr = W_ph + o * 512;
    float acc = b_ph[o];
#pragma unroll 8
    for (int k = 0; k < 512; ++k) acc += hs[k] * wr[k];
    out[b * 256 + o] = acc;
}

extern "C" void kernel_launch(void* const* d_in, const int* in_sizes, int n_in,
                              void* d_out, int out_size) {
    (void)in_sizes; (void)n_in; (void)out_size;
    const float* x    = (const float*)d_in[0];
    const float* W_ix = (const float*)d_in[1];
    const float* W_fx = (const float*)d_in[2];
    const float* W_ox = (const float*)d_in[3];
    const float* W_gx = (const float*)d_in[4];
    const float* W_ih = (const float*)d_in[5];
    const float* b_ih = (const float*)d_in[6];
    const float* W_fh = (const float*)d_in[7];
    const float* b_fh = (const float*)d_in[8];
    const float* W_oh = (const float*)d_in[9];
    const float* b_oh = (const float*)d_in[10];
    const float* W_gh = (const float*)d_in[11];
    const float* b_gh = (const float*)d_in[12];
    const float* W_ph = (const float*)d_in[13];
    const float* b_ph = (const float*)d_in[14];

    size_t smem = (size_t)SMEM_FLOATS * sizeof(float); // 226048 B
    cudaFuncSetAttribute(lstm_persist, cudaFuncAttributeMaxDynamicSharedMemorySize, (int)smem);

    init_k<<<256, 256>>>();
    lstm_persist<<<128, TB, smem>>>(x, W_ix, W_fx, W_ox, W_gx,
                                    W_ih, b_ih, W_fh, b_fh, W_oh, b_oh, W_gh, b_gh);
    proj_k<<<128, 256>>>(W_ph, b_ph, (float*)d_out);
}